// round 6
// baseline (speedup 1.0000x reference)
#include <cuda_runtime.h>
#include <cstdint>
#include <cfloat>

// Problem constants (fixed by dataset)
#define NN    2048
#define TT    128
#define KSEL  20
#define MAXA  20
#define LRC   0.01f
#define EPSC  1e-8f
#define NW32  (NN/32)
#define QSPL  2            // i-range splits per step in k_main
#define ISEG  (NN/QSPL)    // 1024
#define MCAP  2560
#define NROWS 4            // sigma rows per k_sum block
#define NSB   (NN/NROWS)   // 512 sum blocks
#define SBST  136          // padded t-stride for s_B (bank-conflict-free)

// ---------------- device scratch ---------------------------------------------
__device__ static float    g_B[(TT - 1) * NN];         // base preds, 1MB
__device__ static int16_t  g_act_idx[TT * MAXA];
__device__ static int      g_act_cnt[TT];
__device__ static int      g_act_cntfull[TT];
__device__ static unsigned g_act_mask[TT * NW32];
__device__ static unsigned g_match[(TT - 1) * MCAP];   // (js | s1<<8 | c2<<16)
__device__ static int      g_match_cnt[TT - 1];
__device__ static float    g_part[(TT - 1) * QSPL * 2];
__device__ static int      g_done[TT - 1];

// ================= K_prep: top-K per token (radix select) ====================
__global__ void __launch_bounds__(256)
k_prep(const int* __restrict__ tokens, const float* __restrict__ proj) {
    const int t    = blockIdx.x;
    const int tid  = threadIdx.x;
    const int lane = tid & 31;
    const int base = tid * 8;

    __shared__ unsigned hist[256];
    __shared__ unsigned s_prefix;
    __shared__ int      s_kk;
    __shared__ unsigned s_mask[NW32];
    __shared__ int      s_cnt;

    const float* row = proj + (size_t)tokens[t] * NN;
    const float4* rv4 = reinterpret_cast<const float4*>(row + base);
    float4 a = rv4[0], b = rv4[1];
    float v[8] = {a.x, a.y, a.z, a.w, b.x, b.y, b.z, b.w};
    unsigned key[8];
    #pragma unroll
    for (int m = 0; m < 8; m++) {
        unsigned u = __float_as_uint(v[m]);
        key[m] = (u >> 31) ? ~u : (u | 0x80000000u);
    }

    if (tid == 0) { s_prefix = 0u; s_kk = KSEL; }
    unsigned prefix = 0u;
    int kk = KSEL;

    #pragma unroll
    for (int bp = 3; bp >= 0; bp--) {
        hist[tid] = 0u;
        __syncthreads();
        #pragma unroll
        for (int m = 0; m < 8; m++) {
            bool match = (bp == 3) || ((key[m] >> ((bp + 1) * 8)) == prefix);
            if (match) atomicAdd(&hist[(key[m] >> (bp * 8)) & 0xFFu], 1u);
        }
        __syncthreads();
        if (tid < 32) {
            const int top = 255 - lane * 8;
            unsigned local = 0;
            unsigned hv[8];
            #pragma unroll
            for (int q = 0; q < 8; q++) { hv[q] = hist[top - q]; local += hv[q]; }
            unsigned incl = local;
            #pragma unroll
            for (int o = 1; o < 32; o <<= 1) {
                unsigned u = __shfl_up_sync(0xFFFFFFFFu, incl, o);
                if (lane >= o) incl += u;
            }
            unsigned excl = incl - local;
            if (excl < (unsigned)kk && incl >= (unsigned)kk) {
                unsigned e = excl;
                #pragma unroll
                for (int q = 0; q < 8; q++) {
                    if (e + hv[q] >= (unsigned)kk) {
                        s_prefix = (prefix << 8) | (unsigned)(top - q);
                        s_kk = kk - (int)e;
                        break;
                    }
                    e += hv[q];
                }
            }
        }
        __syncthreads();
        prefix = s_prefix;
        kk = s_kk;
    }
    const unsigned key_thr = prefix;

    if (tid < NW32) s_mask[tid] = 0u;
    if (tid == 0)   s_cnt = 0;
    __syncthreads();

    #pragma unroll
    for (int m = 0; m < 8; m++) {
        if (key[m] >= key_thr) {
            int i = base + m;
            atomicOr(&s_mask[i >> 5], 1u << (i & 31));
            int p = atomicAdd(&s_cnt, 1);
            if (p < MAXA) g_act_idx[t * MAXA + p] = (int16_t)i;
        }
    }
    __syncthreads();

    const int cc = (s_cnt < MAXA) ? s_cnt : MAXA;
    if (tid >= cc && tid < MAXA) g_act_idx[t * MAXA + tid] = 0;

    if (tid < NW32) g_act_mask[t * NW32 + tid] = s_mask[tid];
    if (tid == 0) {
        g_act_cntfull[t] = s_cnt;
        g_act_cnt[t]     = cc;
        if (t < TT - 1) g_done[t] = 0;
    }
}

// ====== K_mid: blocks 0..NSB-1 stream sigma -> g_B; blocks NSB.. match lists =
__global__ void __launch_bounds__(256)
k_mid(const float* __restrict__ S, const int* __restrict__ plast) {
    const int bx  = blockIdx.x;
    const int tid = threadIdx.x;
    __shared__ __align__(16) char s_raw[40704];

    if (bx < NSB) {
        // ------- sum panel: rows i0..i0+3, accumulate B[t][i] -------
        float*    panel = reinterpret_cast<float*>(s_raw);              // 32768 B
        int16_t*  idx   = reinterpret_cast<int16_t*>(s_raw + 32768);    // 5120 B
        uint8_t*  acnt  = reinterpret_cast<uint8_t*>(s_raw + 37888);    // 128 B
        float*    sB    = reinterpret_cast<float*>(s_raw + 38016);      // 2176 B

        const int i0 = bx * NROWS;
        // stage sigma panel (coalesced float4)
        #pragma unroll
        for (int il = 0; il < NROWS; il++) {
            const float4* src =
                reinterpret_cast<const float4*>(S + (size_t)(i0 + il) * NN);
            float4* dst = reinterpret_cast<float4*>(panel + il * NN);
            for (int x = tid; x < NN / 4; x += 256) dst[x] = src[x];
        }
        for (int x = tid; x < TT * MAXA / 2; x += 256)
            reinterpret_cast<int*>(idx)[x] =
                reinterpret_cast<const int*>(g_act_idx)[x];
        if (tid < TT) acnt[tid] = (uint8_t)g_act_cnt[tid];
        for (int x = tid; x < NROWS * SBST; x += 256) sB[x] = 0.f;
        __syncthreads();

        // accumulate: w = m*512 + t*4 + il  (t padded to 128)
        for (int w = tid; w < 32 * 512; w += 256) {
            const int m  = w >> 9;
            const int r  = w & 511;
            const int t  = r >> 2;
            const int il = r & 3;
            if (t < TT - 1 && m < (int)acnt[t]) {
                const int j = (int)idx[t * MAXA + m];
                atomicAdd(&sB[il * SBST + t], panel[il * NN + j]);
            }
        }
        __syncthreads();

        // write out partial rows of B
        for (int w = tid; w < (TT - 1) * NROWS; w += 256) {
            const int t  = w >> 2;
            const int il = w & 3;
            g_B[t * NN + i0 + il] = sB[il * SBST + t];
        }
        return;
    }

    // ------- match list for t = bx - NSB -------
    const int t = bx - NSB;
    int16_t* idx   = reinterpret_cast<int16_t*>(s_raw);            // 5120
    uint8_t* acnt  = reinterpret_cast<uint8_t*>(s_raw + 5120);     // 128
    uint8_t* pos   = reinterpret_cast<uint8_t*>(s_raw + 5248);     // 2048
    int*     cntp  = reinterpret_cast<int*>(s_raw + 7296);

    if (!*plast) { if (tid == 0) g_match_cnt[t] = 0; return; }

    for (int x = tid; x < TT * MAXA / 2; x += 256)
        reinterpret_cast<int*>(idx)[x] = reinterpret_cast<const int*>(g_act_idx)[x];
    if (tid < TT) acnt[tid] = (uint8_t)g_act_cnt[tid];
    for (int x = tid; x < NN / 4; x += 256)
        reinterpret_cast<unsigned*>(pos)[x] = 0xFFFFFFFFu;
    if (tid == 0) *cntp = 0;
    __syncthreads();

    const int cnt_t = acnt[t];
    if (tid < cnt_t) pos[(int)idx[t * MAXA + tid]] = (uint8_t)tid;
    __syncthreads();

    for (int wk = tid; wk < t * 32; wk += 256) {
        const int s = wk >> 5;
        const int m = wk & 31;
        if (m < acnt[s]) {
            const int j  = idx[s * MAXA + m];
            const int js = pos[j];
            if (js != 0xFF) {
                const int p = atomicAdd(cntp, 1);
                g_match[t * MCAP + p] =
                    (unsigned)js | ((unsigned)(s + 1) << 8) |
                    ((unsigned)acnt[s + 1] << 16);
            }
        }
    }
    __syncthreads();
    if (tid == 0) g_match_cnt[t] = *cntp;
}

// ================= K_main: QSPL CTAs per step t ===============================
__global__ void __launch_bounds__(256)
k_main(const float* __restrict__ S0, const int* __restrict__ plast,
       float* __restrict__ out) {
    const int bx   = blockIdx.x;
    const int t    = bx >> 1;          // 0..126
    const int q    = bx & (QSPL - 1);
    const int lo   = q * ISEG;
    const int tid  = threadIdx.x;      // 256
    const int lane = tid & 31;
    const int w    = tid >> 5;
    const int i0   = lo + tid * 4;

    __shared__ unsigned s_cntw[MAXA * ISEG / 4];   // 20480 B packed byte counts
    __shared__ float    s_red[16];

    const int plasticity = *plast;

    if (plasticity)
        for (int x = tid; x < MAXA * ISEG / 4; x += 256) s_cntw[x] = 0u;

    // phase 1: base pred = one coalesced float4 from g_B
    const float4 b4 = *reinterpret_cast<const float4*>(g_B + t * NN + i0);
    float p[4] = {b4.x, b4.y, b4.z, b4.w};

    if (plasticity) {
        __syncthreads();   // counters zeroed before atomics

        // phase 2: expand precomputed match list into counts
        const int nm = g_match_cnt[t];
        for (int e = tid; e < nm; e += 256) {
            const unsigned ent = g_match[t * MCAP + e];
            const int js = (int)(ent & 0xFFu);
            const int b2 = (int)((ent >> 8) & 0xFFu) * MAXA;
            const int c2 = (int)(ent >> 16);
            for (int mm = 0; mm < c2; mm++) {
                const int i = (int)g_act_idx[b2 + mm];
                const unsigned d = (unsigned)(i - lo);
                if (d < (unsigned)ISEG)
                    atomicAdd(&s_cntw[((unsigned)js * ISEG + d) >> 2],
                              1u << ((d & 3u) * 8u));
            }
        }
        __syncthreads();

        // phase 3: sparse clip corrections (scattered S0 reads, rare)
        #pragma unroll
        for (int js = 0; js < MAXA; js++) {
            const unsigned word = s_cntw[(unsigned)js * (ISEG / 4) + tid];
            if (word) {
                const int j = (int)g_act_idx[t * MAXA + js];
                #pragma unroll
                for (int c = 0; c < 4; c++) {
                    const unsigned cc = (word >> (c * 8)) & 0xFFu;
                    if (cc) {
                        const float v = S0[(size_t)(i0 + c) * NN + j];
                        p[c] += fminf(v + LRC * (float)cc, 1.0f) - v;
                    }
                }
            }
        }
    }

    // reduction over segment
    const unsigned mword = g_act_mask[(t + 1) * NW32 + (i0 >> 5)];
    const unsigned nib   = (mword >> (i0 & 31)) & 0xFu;
    float pn2 = 0.f, dt = 0.f;
    #pragma unroll
    for (int c = 0; c < 4; c++) {
        pn2 += p[c] * p[c];
        if ((nib >> c) & 1u) dt += p[c];
    }
    #pragma unroll
    for (int o = 16; o; o >>= 1) {
        pn2 += __shfl_xor_sync(0xFFFFFFFFu, pn2, o);
        dt  += __shfl_xor_sync(0xFFFFFFFFu, dt, o);
    }
    if (lane == 0) { s_red[2 * w] = pn2; s_red[2 * w + 1] = dt; }
    __syncthreads();

    if (tid == 0) {
        float P2 = 0.f, D = 0.f;
        #pragma unroll
        for (int r = 0; r < 8; r++) { P2 += s_red[2 * r]; D += s_red[2 * r + 1]; }
        g_part[(t * QSPL + q) * 2 + 0] = P2;
        g_part[(t * QSPL + q) * 2 + 1] = D;
        __threadfence();
        const int d = atomicAdd(&g_done[t], 1);
        if (d == QSPL - 1) {
            __threadfence();
            float TP2 = 0.f, TD = 0.f;
            #pragma unroll
            for (int s = 0; s < QSPL; s++) {
                TP2 += g_part[(t * QSPL + s) * 2 + 0];
                TD  += g_part[(t * QSPL + s) * 2 + 1];
            }
            const float pn = sqrtf(TP2);
            float tension;
            if (plasticity) {
                const float overlap = TD / (pn * sqrtf((float)KSEL) + EPSC);
                tension = (pn > 0.0f) ? (1.0f - overlap) : 1.0f;
            } else {
                const float xn = sqrtf((float)g_act_cntfull[t + 1]);
                tension = 1.0f - TD / (pn * xn + EPSC);
            }
            out[t] = tension;
        }
    }
}

// ---------------- launch ------------------------------------------------------
extern "C" void kernel_launch(void* const* d_in, const int* in_sizes, int n_in,
                              void* d_out, int out_size) {
    const int*   tokens = (const int*)d_in[0];
    const float* proj   = (const float*)d_in[1];
    const float* sigma  = (const float*)d_in[2];
    const int*   plast  = (const int*)d_in[3];
    float*       out    = (float*)d_out;

    k_prep<<<TT, 256>>>(tokens, proj);
    k_mid<<<NSB + (TT - 1), 256>>>(sigma, plast);
    k_main<<<(TT - 1) * QSPL, 256>>>(sigma, plast, out);
}